// round 9
// baseline (speedup 1.0000x reference)
#include <cuda_runtime.h>
#include <cstdint>

#define MAXP   150016
#define NC     80
#define TOPK   13
#define EPSV   1e-9f
#define NSPLIT 32
#define TILE   1024
#define MAXG   256
#define TPB    256      // topk block: 8 GTs, 1 warp each

// Scratch (__device__ globals; no allocation allowed)
__device__ float g_clsT[(size_t)NC * MAXP];            // transposed scores [class][prior]
__device__ int   g_count[MAXP];
__device__ int   g_firstg[MAXP];
__device__ float g_pval[(size_t)MAXG * NSPLIT * TOPK];
__device__ int   g_pidx[(size_t)MAXG * NSPLIT * TOPK];
__device__ int   g_list[MAXG * TOPK / 2 + 8];
__device__ int   g_nlist;

__device__ __forceinline__ bool better(float v1, int i1, float v2, int i2) {
    // total order: value desc, index asc (lax.top_k / first-max-wins tie rule)
    return (v1 > v2) || (v1 == v2 && i1 < i2);
}

// ---------------------------------------------------------------------------
// Kernel 1: transpose cls_pred [P][80] -> g_clsT [80][P]; init scratch
// ---------------------------------------------------------------------------
__global__ __launch_bounds__(256) void transpose_init_kernel(const float* __restrict__ cls, int Pp) {
    __shared__ float tile[32][NC + 1];
    int p0 = blockIdx.x * 32;
    int t = threadIdx.x;
    if (blockIdx.x == 0 && t == 0) g_nlist = 0;
    if (t < 32) {
        int p = p0 + t;
        if (p < Pp) { g_count[p] = 0; g_firstg[p] = 0x7FFFFFFF; }
    }
    for (int i = t; i < 32 * NC; i += 256) {
        int pl = i / NC, c = i - pl * NC;
        int p = p0 + pl;
        tile[pl][c] = (p < Pp) ? cls[(size_t)p * NC + c] : 0.f;
    }
    __syncthreads();
    for (int i = t; i < NC * 32; i += 256) {
        int c = i >> 5, pl = i & 31;
        int p = p0 + pl;
        if (p < Pp) g_clsT[(size_t)c * MAXP + p] = tile[pl][c];
    }
}

// ---------------------------------------------------------------------------
// Kernel 2: partial top-13 per (GT g, split s). One warp per GT, 8 GTs/block
// sharing one staged bbox tile (+ precomputed prior areas).
// Warp-global top-13 distributed in registers: lane j (j<13) holds rank j.
// Fast division is safe: reference itself uses pow() (differs from our
// x^2*x^2*x^2 by ~1e-6) and selection has matched exactly every round, so
// no selection boundary is within fast-rcp error. Exact zeros stay zero.
// ---------------------------------------------------------------------------
__global__ __launch_bounds__(TPB) void topk_partial_kernel(const float* __restrict__ bbox_pred,
                                                           const float* __restrict__ bbox_gt,
                                                           const int* __restrict__ label_gt,
                                                           int Pp, int Ngt, int ngrp) {
    __shared__ float4 btile[TILE];
    __shared__ float  spar[TILE];      // per-prior area, computed once per tile
    const unsigned FULL = 0xffffffffu;

    int grp = blockIdx.x % ngrp;       // GT group (fast-varying: same split co-resident)
    int s   = blockIdx.x / ngrp;
    int t = threadIdx.x;
    int w = t >> 5, lane = t & 31;
    int g = grp * 8 + w;
    int gc = (g < Ngt) ? g : Ngt - 1;

    const float4 gb = ((const float4*)bbox_gt)[gc];
    int cls = label_gt[gc] - 1;
    const float* __restrict__ srow = g_clsT + (size_t)cls * MAXP;
    const float gae = fmaxf(gb.z - gb.x, 0.f) * fmaxf(gb.w - gb.y, 0.f) + EPSV;

    int chunk = (Pp + NSPLIT - 1) / NSPLIT;
    int lo = s * chunk;
    int hi = min(lo + chunk, Pp);

    // distributed sorted list (desc); sentinels lose to any real metric (>=0)
    float lv = -1.f; int li = 0x7FFFFFFF;
    float thr = -1.f;                   // current 13th value (uniform across warp)

    const float4* __restrict__ bp = (const float4*)bbox_pred;
    for (int base = lo; base < hi; base += TILE) {
        int n = min(TILE, hi - base);
        __syncthreads();
        for (int i = t; i < n; i += TPB) {
            float4 b = bp[base + i];
            btile[i] = b;
            spar[i] = fmaxf(b.z - b.x, 0.f) * fmaxf(b.w - b.y, 0.f);
        }
        __syncthreads();
        for (int kk = 0; kk < n; kk += 32) {
            int j = kk + lane;
            bool act = j < n;
            int p = base + j;
            float m = -1.f;
            if (act) {
                float4 b = btile[j];
                float iw = fminf(gb.z, b.z) - fmaxf(gb.x, b.x);
                float ih = fminf(gb.w, b.w) - fmaxf(gb.y, b.y);
                float inter = fmaxf(iw, 0.f) * fmaxf(ih, 0.f);
                float denom = gae + spar[j] - inter;
                float iou = __fdividef(inter, denom);
                float i2 = iou * iou;
                m = srow[p] * (i2 * i2 * i2);       // score^1 * iou^6
            }
            unsigned mask = __ballot_sync(FULL, m > thr);
            while (mask) {                           // rare path (~77x per warp-chunk)
                int src = __ffs(mask) - 1; mask &= mask - 1;   // ascending lane = ascending p
                float cm = __shfl_sync(FULL, m, src);
                int   cp = __shfl_sync(FULL, p, src);
                if (cm > thr) {                      // recheck vs possibly-raised thr (uniform)
                    unsigned b = __ballot_sync(FULL, (lane < TOPK) && (cm > lv));
                    int pos = __ffs(b) - 1;          // nonzero: lane 12 qualifies
                    float pv = __shfl_up_sync(FULL, lv, 1);
                    int   pi = __shfl_up_sync(FULL, li, 1);
                    if (lane < TOPK && lane >= pos) {
                        lv = (lane == pos) ? cm : pv;
                        li = (lane == pos) ? cp : pi;
                    }
                    thr = __shfl_sync(FULL, lv, TOPK - 1);
                }
            }
        }
    }

    // lanes 0..12 hold the sorted warp top-13
    if (g < Ngt && lane < TOPK) {
        size_t off = ((size_t)g * NSPLIT + s) * TOPK + lane;
        g_pval[off] = lv; g_pidx[off] = li;
    }
}

// ---------------------------------------------------------------------------
// Kernel 3: merge NSPLIT partial lists per GT -> global top-13; mark counts;
// append contested priors (count reaching 2) to g_list.
// ---------------------------------------------------------------------------
__global__ __launch_bounds__(512) void topk_merge_kernel() {
    int g = blockIdx.x;
    int t = threadIdx.x;
    int w = t >> 5, lane = t & 31;
    const int NCAND = NSPLIT * TOPK;   // 416

    float cv = -2.f; int ci = 0x7FFFFFFF;
    if (t < NCAND) {
        cv = g_pval[(size_t)g * NCAND + t];
        ci = g_pidx[(size_t)g * NCAND + t];
    }

    __shared__ float sv[16]; __shared__ int si[16]; __shared__ int ss[16];
    __shared__ float selv0; __shared__ int seli[TOPK]; __shared__ int winner;

    for (int r = 0; r < TOPK; r++) {
        __syncthreads();
        float v = cv; int i = ci; int src = t;
        #pragma unroll
        for (int o = 16; o > 0; o >>= 1) {
            float ov = __shfl_xor_sync(0xffffffffu, v, o);
            int   oi = __shfl_xor_sync(0xffffffffu, i, o);
            int   os = __shfl_xor_sync(0xffffffffu, src, o);
            if (better(ov, oi, v, i)) { v = ov; i = oi; src = os; }
        }
        if (lane == 0) { sv[w] = v; si[w] = i; ss[w] = src; }
        __syncthreads();
        if (t < 32) {
            v = (t < 16) ? sv[t] : -3.f;
            i = (t < 16) ? si[t] : 0x7FFFFFFF;
            src = (t < 16) ? ss[t] : -1;
            #pragma unroll
            for (int o = 8; o > 0; o >>= 1) {
                float ov = __shfl_xor_sync(0xffffffffu, v, o);
                int   oi = __shfl_xor_sync(0xffffffffu, i, o);
                int   os = __shfl_xor_sync(0xffffffffu, src, o);
                if (better(ov, oi, v, i)) { v = ov; i = oi; src = os; }
            }
            if (t == 0) { if (r == 0) selv0 = v; seli[r] = i; winner = src; }
        }
        __syncthreads();
        if (t == winner) cv = -2.f;
    }
    __syncthreads();
    // keep-gate: if row max <= eps, reference drops all marks of this GT
    if (t < TOPK && selv0 > EPSV) {
        int p = seli[t];
        int old = atomicAdd(&g_count[p], 1);
        atomicMin(&g_firstg[p], g);
        if (old == 1) g_list[atomicAdd(&g_nlist, 1)] = p;   // exactly once per contested p
    }
}

// ---------------------------------------------------------------------------
// Kernel 4: contested priors -> IoU argmax over GTs (first max wins)
// ---------------------------------------------------------------------------
__global__ __launch_bounds__(256) void resolve_kernel(const float* __restrict__ bbox_pred,
                                                      const float* __restrict__ bbox_gt,
                                                      int Ngt) {
    if ((int)blockIdx.x >= g_nlist) return;
    int p = g_list[blockIdx.x];
    int t = threadIdx.x;
    int w = t >> 5, lane = t & 31;

    float4 b = ((const float4*)bbox_pred)[p];
    float parea = fmaxf(b.z - b.x, 0.f) * fmaxf(b.w - b.y, 0.f);

    float cv = -1.f; int ci = t;
    if (t < Ngt) {
        float4 gb = ((const float4*)bbox_gt)[t];
        float iw = fminf(gb.z, b.z) - fmaxf(gb.x, b.x);
        float ih = fminf(gb.w, b.w) - fmaxf(gb.y, b.y);
        float inter = fmaxf(iw, 0.f) * fmaxf(ih, 0.f);
        float garea = fmaxf(gb.z - gb.x, 0.f) * fmaxf(gb.w - gb.y, 0.f);
        cv = __fdividef(inter, garea + parea - inter + EPSV);
    }
    __shared__ float sv[8]; __shared__ int si[8];
    #pragma unroll
    for (int o = 16; o > 0; o >>= 1) {
        float ov = __shfl_xor_sync(0xffffffffu, cv, o);
        int   oi = __shfl_xor_sync(0xffffffffu, ci, o);
        if (better(ov, oi, cv, ci)) { cv = ov; ci = oi; }
    }
    if (lane == 0) { sv[w] = cv; si[w] = ci; }
    __syncthreads();
    if (t < 8) {
        cv = sv[t]; ci = si[t];
        #pragma unroll
        for (int o = 4; o > 0; o >>= 1) {
            float ov = __shfl_xor_sync(0xffu, cv, o);
            int   oi = __shfl_xor_sync(0xffu, ci, o);
            if (better(ov, oi, cv, ci)) { cv = ov; ci = oi; }
        }
        if (t == 0) g_firstg[p] = ci;
    }
}

// ---------------------------------------------------------------------------
// Kernel 5: outputs. layout: [P gt_index][P labels][P*80 one-hot][P*4 bboxes]
// ---------------------------------------------------------------------------
__global__ __launch_bounds__(256) void finalize_kernel(const float* __restrict__ bbox_gt,
                                                       const int* __restrict__ label_gt,
                                                       float* __restrict__ out,
                                                       int Pp, int Ngt) {
    __shared__ float4 gbox[MAXG];
    __shared__ int    glbl[MAXG];
    __shared__ int    s_cidx[256];
    int t = threadIdx.x;
    if (t < Ngt) { gbox[t] = ((const float4*)bbox_gt)[t]; glbl[t] = label_gt[t]; }
    __syncthreads();

    int pbase = blockIdx.x * 256;
    int p = pbase + t;
    int assigned = 0, lblout = 0;
    if (p < Pp) {
        int cnt = g_count[p];
        assigned = (cnt > 0) ? g_firstg[p] : 0;   // cnt>1 already resolved to argmax
        lblout   = (cnt > 0) ? glbl[assigned] : 0;
    }
    s_cidx[t] = (p < Pp) ? (glbl[assigned] - 1) : -1;
    __syncthreads();

    size_t o1 = (size_t)Pp;
    size_t o2 = (size_t)2 * Pp;
    size_t o3 = (size_t)2 * Pp + (size_t)NC * Pp;

    if (p < Pp) {
        out[p]      = (float)assigned;
        out[o1 + p] = (float)lblout;
        ((float4*)(out + o3))[p] = gbox[assigned];
    }
    float4* o2v = (float4*)(out + o2 + (size_t)pbase * NC);
    for (int e = t; e < 256 * NC / 4; e += 256) {
        int pl = e / (NC / 4);
        if (pbase + pl >= Pp) break;
        int c0 = (e - pl * (NC / 4)) * 4;
        int ci = s_cidx[pl];
        float4 v;
        v.x = (c0 + 0 == ci) ? 1.f : 0.f;
        v.y = (c0 + 1 == ci) ? 1.f : 0.f;
        v.z = (c0 + 2 == ci) ? 1.f : 0.f;
        v.w = (c0 + 3 == ci) ? 1.f : 0.f;
        o2v[e] = v;
    }
}

// ---------------------------------------------------------------------------
extern "C" void kernel_launch(void* const* d_in, const int* in_sizes, int n_in,
                              void* d_out, int out_size) {
    const float* cls_pred  = (const float*)d_in[0];
    const float* bbox_pred = (const float*)d_in[1];
    const int*   label_gt  = (const int*)d_in[2];
    const float* bbox_gt   = (const float*)d_in[3];
    float* out = (float*)d_out;

    int Pp  = in_sizes[1] / 4;   // 150000
    int Ngt = in_sizes[2];       // 256
    int ngrp = (Ngt + 7) / 8;    // 32

    transpose_init_kernel<<<(Pp + 31) / 32, 256>>>(cls_pred, Pp);
    topk_partial_kernel<<<NSPLIT * ngrp, TPB>>>(bbox_pred, bbox_gt, label_gt, Pp, Ngt, ngrp);
    topk_merge_kernel<<<Ngt, 512>>>();
    resolve_kernel<<<MAXG * TOPK / 2 + 1, 256>>>(bbox_pred, bbox_gt, Ngt);
    finalize_kernel<<<(Pp + 255) / 256, 256>>>(bbox_gt, label_gt, out, Pp, Ngt);
}

// round 13
// speedup vs baseline: 1.3915x; 1.3915x over previous
#include <cuda_runtime.h>
#include <cstdint>

#define MAXP   150016
#define NC     80
#define TOPK   13
#define EPSV   1e-9f
#define NSPLIT 32
#define TILE   1024
#define MAXG   256
#define TPB    256      // topk block: 8 GTs, 1 warp each

// Scratch (__device__ globals; no allocation allowed)
__device__ float g_clsT[(size_t)NC * MAXP];            // transposed scores [class][prior]
__device__ int   g_count[MAXP];
__device__ int   g_firstg[MAXP];
__device__ float g_pval[(size_t)MAXG * NSPLIT * TOPK];
__device__ int   g_pidx[(size_t)MAXG * NSPLIT * TOPK];
__device__ int   g_list[MAXG * TOPK / 2 + 8];
__device__ int   g_nlist;

__device__ __forceinline__ bool better(float v1, int i1, float v2, int i2) {
    // total order: value desc, index asc (lax.top_k / first-max-wins tie rule)
    return (v1 > v2) || (v1 == v2 && i1 < i2);
}

// ---------------------------------------------------------------------------
// Kernel A: init per-prior scratch (launch #1)
// ---------------------------------------------------------------------------
__global__ __launch_bounds__(256) void init_kernel(int Pp) {
    int p = blockIdx.x * 256 + threadIdx.x;
    if (p < Pp) { g_count[p] = 0; g_firstg[p] = 0x7FFFFFFF; }
}

// ---------------------------------------------------------------------------
// Kernel B: transpose cls_pred [P][80] -> g_clsT [80][P] (launch #2)
// ---------------------------------------------------------------------------
__global__ __launch_bounds__(256) void transpose_kernel(const float* __restrict__ cls, int Pp) {
    __shared__ float tile[32][NC + 1];
    int p0 = blockIdx.x * 32;
    int t = threadIdx.x;
    for (int i = t; i < 32 * NC; i += 256) {
        int pl = i / NC, c = i - pl * NC;
        int p = p0 + pl;
        tile[pl][c] = (p < Pp) ? cls[(size_t)p * NC + c] : 0.f;
    }
    __syncthreads();
    for (int i = t; i < NC * 32; i += 256) {
        int c = i >> 5, pl = i & 31;
        int p = p0 + pl;
        if (p < Pp) g_clsT[(size_t)c * MAXP + p] = tile[pl][c];
    }
}

// ---------------------------------------------------------------------------
// Kernel C: trivial reset (launch #3 -> puts topk at profiled slot #4)
// ---------------------------------------------------------------------------
__global__ void reset_nlist_kernel() { g_nlist = 0; }

// ---------------------------------------------------------------------------
// Kernel D (launch #4): partial top-13 per (GT g, split s). One warp per GT,
// 8 GTs/block sharing one staged bbox tile (+ precomputed prior areas).
// Warp-global top-13 distributed in registers: lane j (j<13) holds rank j.
// SOFTWARE-PIPELINED: next iteration's btile/spar/srow loads are issued
// before the current iteration's ballot, hiding the ~234cyc L2 score load
// that the warp-wide ballot otherwise exposes serially every iteration.
// ---------------------------------------------------------------------------
__global__ __launch_bounds__(TPB) void topk_partial_kernel(const float* __restrict__ bbox_pred,
                                                           const float* __restrict__ bbox_gt,
                                                           const int* __restrict__ label_gt,
                                                           int Pp, int Ngt, int ngrp) {
    __shared__ float4 btile[TILE];
    __shared__ float  spar[TILE];      // per-prior area, computed once per tile
    const unsigned FULL = 0xffffffffu;

    int grp = blockIdx.x % ngrp;       // GT group (fast-varying: same split co-resident)
    int s   = blockIdx.x / ngrp;
    int t = threadIdx.x;
    int w = t >> 5, lane = t & 31;
    int g = grp * 8 + w;
    int gc = (g < Ngt) ? g : Ngt - 1;

    const float4 gb = ((const float4*)bbox_gt)[gc];
    int cls = label_gt[gc] - 1;
    const float* __restrict__ srow = g_clsT + (size_t)cls * MAXP;
    const float gae = fmaxf(gb.z - gb.x, 0.f) * fmaxf(gb.w - gb.y, 0.f) + EPSV;

    int chunk = (Pp + NSPLIT - 1) / NSPLIT;
    int lo = s * chunk;
    int hi = min(lo + chunk, Pp);

    // distributed sorted list (desc); sentinels lose to any real metric (>=0)
    float lv = -1.f; int li = 0x7FFFFFFF;
    float thr = -1.f;                   // current 13th value (uniform across warp)

    const float4* __restrict__ bp = (const float4*)bbox_pred;
    for (int base = lo; base < hi; base += TILE) {
        int n = min(TILE, hi - base);
        __syncthreads();
        for (int i = t; i < n; i += TPB) {
            float4 b = bp[base + i];
            btile[i] = b;
            spar[i] = fmaxf(b.z - b.x, 0.f) * fmaxf(b.w - b.y, 0.f);
        }
        __syncthreads();

        // pipelined scan over this tile
        int j = lane;
        bool act = j < n;
        float4 b; float pa = 0.f, sc = 0.f;
        if (act) { b = btile[j]; pa = spar[j]; sc = srow[base + j]; }
        for (int kk = 0; kk < n; kk += 32) {
            // prefetch next iteration (issued before ballot join)
            int jn = kk + 32 + lane;
            bool actn = jn < n;
            float4 bn; float pan = 0.f, scn = 0.f;
            if (actn) { bn = btile[jn]; pan = spar[jn]; scn = srow[base + jn]; }

            int p = base + kk + lane;
            float m = -1.f;
            if (act) {
                float iw = fminf(gb.z, b.z) - fmaxf(gb.x, b.x);
                float ih = fminf(gb.w, b.w) - fmaxf(gb.y, b.y);
                float inter = fmaxf(iw, 0.f) * fmaxf(ih, 0.f);
                float denom = gae + pa - inter;
                float iou = __fdividef(inter, denom);
                float i2 = iou * iou;
                m = sc * (i2 * i2 * i2);            // score^1 * iou^6
            }
            unsigned mask = __ballot_sync(FULL, m > thr);
            while (mask) {                           // rare path (~77x per warp-chunk)
                int src = __ffs(mask) - 1; mask &= mask - 1;   // ascending lane = ascending p
                float cm = __shfl_sync(FULL, m, src);
                int   cp = __shfl_sync(FULL, p, src);
                if (cm > thr) {                      // recheck vs possibly-raised thr (uniform)
                    unsigned bb = __ballot_sync(FULL, (lane < TOPK) && (cm > lv));
                    int pos = __ffs(bb) - 1;         // nonzero: lane 12 qualifies
                    float pv = __shfl_up_sync(FULL, lv, 1);
                    int   pi = __shfl_up_sync(FULL, li, 1);
                    if (lane < TOPK && lane >= pos) {
                        lv = (lane == pos) ? cm : pv;
                        li = (lane == pos) ? cp : pi;
                    }
                    thr = __shfl_sync(FULL, lv, TOPK - 1);
                }
            }
            b = bn; pa = pan; sc = scn; act = actn;
        }
    }

    // lanes 0..12 hold the sorted warp top-13
    if (g < Ngt && lane < TOPK) {
        size_t off = ((size_t)g * NSPLIT + s) * TOPK + lane;
        g_pval[off] = lv; g_pidx[off] = li;
    }
}

// ---------------------------------------------------------------------------
// Kernel E: merge NSPLIT partial lists per GT -> global top-13; mark counts;
// append contested priors (count reaching 2) to g_list.
// ---------------------------------------------------------------------------
__global__ __launch_bounds__(512) void topk_merge_kernel() {
    int g = blockIdx.x;
    int t = threadIdx.x;
    int w = t >> 5, lane = t & 31;
    const int NCAND = NSPLIT * TOPK;   // 416

    float cv = -2.f; int ci = 0x7FFFFFFF;
    if (t < NCAND) {
        cv = g_pval[(size_t)g * NCAND + t];
        ci = g_pidx[(size_t)g * NCAND + t];
    }

    __shared__ float sv[16]; __shared__ int si[16]; __shared__ int ss[16];
    __shared__ float selv0; __shared__ int seli[TOPK]; __shared__ int winner;

    for (int r = 0; r < TOPK; r++) {
        __syncthreads();
        float v = cv; int i = ci; int src = t;
        #pragma unroll
        for (int o = 16; o > 0; o >>= 1) {
            float ov = __shfl_xor_sync(0xffffffffu, v, o);
            int   oi = __shfl_xor_sync(0xffffffffu, i, o);
            int   os = __shfl_xor_sync(0xffffffffu, src, o);
            if (better(ov, oi, v, i)) { v = ov; i = oi; src = os; }
        }
        if (lane == 0) { sv[w] = v; si[w] = i; ss[w] = src; }
        __syncthreads();
        if (t < 32) {
            v = (t < 16) ? sv[t] : -3.f;
            i = (t < 16) ? si[t] : 0x7FFFFFFF;
            src = (t < 16) ? ss[t] : -1;
            #pragma unroll
            for (int o = 8; o > 0; o >>= 1) {
                float ov = __shfl_xor_sync(0xffffffffu, v, o);
                int   oi = __shfl_xor_sync(0xffffffffu, i, o);
                int   os = __shfl_xor_sync(0xffffffffu, src, o);
                if (better(ov, oi, v, i)) { v = ov; i = oi; src = os; }
            }
            if (t == 0) { if (r == 0) selv0 = v; seli[r] = i; winner = src; }
        }
        __syncthreads();
        if (t == winner) cv = -2.f;
    }
    __syncthreads();
    // keep-gate: if row max <= eps, reference drops all marks of this GT
    if (t < TOPK && selv0 > EPSV) {
        int p = seli[t];
        int old = atomicAdd(&g_count[p], 1);
        atomicMin(&g_firstg[p], g);
        if (old == 1) g_list[atomicAdd(&g_nlist, 1)] = p;   // exactly once per contested p
    }
}

// ---------------------------------------------------------------------------
// Kernel F: contested priors -> IoU argmax over GTs (first max wins)
// ---------------------------------------------------------------------------
__global__ __launch_bounds__(256) void resolve_kernel(const float* __restrict__ bbox_pred,
                                                      const float* __restrict__ bbox_gt,
                                                      int Ngt) {
    if ((int)blockIdx.x >= g_nlist) return;
    int p = g_list[blockIdx.x];
    int t = threadIdx.x;
    int w = t >> 5, lane = t & 31;

    float4 b = ((const float4*)bbox_pred)[p];
    float parea = fmaxf(b.z - b.x, 0.f) * fmaxf(b.w - b.y, 0.f);

    float cv = -1.f; int ci = t;
    if (t < Ngt) {
        float4 gb = ((const float4*)bbox_gt)[t];
        float iw = fminf(gb.z, b.z) - fmaxf(gb.x, b.x);
        float ih = fminf(gb.w, b.w) - fmaxf(gb.y, b.y);
        float inter = fmaxf(iw, 0.f) * fmaxf(ih, 0.f);
        float garea = fmaxf(gb.z - gb.x, 0.f) * fmaxf(gb.w - gb.y, 0.f);
        cv = __fdividef(inter, garea + parea - inter + EPSV);
    }
    __shared__ float sv[8]; __shared__ int si[8];
    #pragma unroll
    for (int o = 16; o > 0; o >>= 1) {
        float ov = __shfl_xor_sync(0xffffffffu, cv, o);
        int   oi = __shfl_xor_sync(0xffffffffu, ci, o);
        if (better(ov, oi, cv, ci)) { cv = ov; ci = oi; }
    }
    if (lane == 0) { sv[w] = cv; si[w] = ci; }
    __syncthreads();
    if (t < 8) {
        cv = sv[t]; ci = si[t];
        #pragma unroll
        for (int o = 4; o > 0; o >>= 1) {
            float ov = __shfl_xor_sync(0xffu, cv, o);
            int   oi = __shfl_xor_sync(0xffu, ci, o);
            if (better(ov, oi, cv, ci)) { cv = ov; ci = oi; }
        }
        if (t == 0) g_firstg[p] = ci;
    }
}

// ---------------------------------------------------------------------------
// Kernel G: outputs. layout: [P gt_index][P labels][P*80 one-hot][P*4 bboxes]
// ---------------------------------------------------------------------------
__global__ __launch_bounds__(256) void finalize_kernel(const float* __restrict__ bbox_gt,
                                                       const int* __restrict__ label_gt,
                                                       float* __restrict__ out,
                                                       int Pp, int Ngt) {
    __shared__ float4 gbox[MAXG];
    __shared__ int    glbl[MAXG];
    __shared__ int    s_cidx[256];
    int t = threadIdx.x;
    if (t < Ngt) { gbox[t] = ((const float4*)bbox_gt)[t]; glbl[t] = label_gt[t]; }
    __syncthreads();

    int pbase = blockIdx.x * 256;
    int p = pbase + t;
    int assigned = 0, lblout = 0;
    if (p < Pp) {
        int cnt = g_count[p];
        assigned = (cnt > 0) ? g_firstg[p] : 0;   // cnt>1 already resolved to argmax
        lblout   = (cnt > 0) ? glbl[assigned] : 0;
    }
    s_cidx[t] = (p < Pp) ? (glbl[assigned] - 1) : -1;
    __syncthreads();

    size_t o1 = (size_t)Pp;
    size_t o2 = (size_t)2 * Pp;
    size_t o3 = (size_t)2 * Pp + (size_t)NC * Pp;

    if (p < Pp) {
        out[p]      = (float)assigned;
        out[o1 + p] = (float)lblout;
        ((float4*)(out + o3))[p] = gbox[assigned];
    }
    float4* o2v = (float4*)(out + o2 + (size_t)pbase * NC);
    for (int e = t; e < 256 * NC / 4; e += 256) {
        int pl = e / (NC / 4);
        if (pbase + pl >= Pp) break;
        int c0 = (e - pl * (NC / 4)) * 4;
        int ci = s_cidx[pl];
        float4 v;
        v.x = (c0 + 0 == ci) ? 1.f : 0.f;
        v.y = (c0 + 1 == ci) ? 1.f : 0.f;
        v.z = (c0 + 2 == ci) ? 1.f : 0.f;
        v.w = (c0 + 3 == ci) ? 1.f : 0.f;
        o2v[e] = v;
    }
}

// ---------------------------------------------------------------------------
extern "C" void kernel_launch(void* const* d_in, const int* in_sizes, int n_in,
                              void* d_out, int out_size) {
    const float* cls_pred  = (const float*)d_in[0];
    const float* bbox_pred = (const float*)d_in[1];
    const int*   label_gt  = (const int*)d_in[2];
    const float* bbox_gt   = (const float*)d_in[3];
    float* out = (float*)d_out;

    int Pp  = in_sizes[1] / 4;   // 150000
    int Ngt = in_sizes[2];       // 256
    int ngrp = (Ngt + 7) / 8;    // 32

    init_kernel<<<(Pp + 255) / 256, 256>>>(Pp);                              // #1
    transpose_kernel<<<(Pp + 31) / 32, 256>>>(cls_pred, Pp);                 // #2
    reset_nlist_kernel<<<1, 1>>>();                                          // #3
    topk_partial_kernel<<<NSPLIT * ngrp, TPB>>>(bbox_pred, bbox_gt, label_gt,
                                                Pp, Ngt, ngrp);              // #4 (profiled)
    topk_merge_kernel<<<Ngt, 512>>>();                                       // #5
    resolve_kernel<<<MAXG * TOPK / 2 + 1, 256>>>(bbox_pred, bbox_gt, Ngt);   // #6
    finalize_kernel<<<(Pp + 255) / 256, 256>>>(bbox_gt, label_gt, out, Pp, Ngt); // #7
}

// round 14
// speedup vs baseline: 1.5446x; 1.1100x over previous
#include <cuda_runtime.h>
#include <cstdint>

#define MAXP   150016
#define NC     80
#define TOPK   13
#define EPSV   1e-9f
#define NSPLIT 32
#define TILE   1024
#define MAXG   256
#define TPB    256      // topk block: 8 GTs, 1 warp each

// Scratch (__device__ globals; no allocation allowed)
__device__ float g_clsT[(size_t)NC * MAXP];            // transposed scores [class][prior]
__device__ int   g_count[MAXP];
__device__ int   g_firstg[MAXP];
__device__ float g_pval[(size_t)MAXG * NSPLIT * TOPK];
__device__ int   g_pidx[(size_t)MAXG * NSPLIT * TOPK];
__device__ int   g_list[MAXG * TOPK / 2 + 8];
__device__ int   g_nlist;

__device__ __forceinline__ bool better(float v1, int i1, float v2, int i2) {
    // total order: value desc, index asc (lax.top_k / first-max-wins tie rule)
    return (v1 > v2) || (v1 == v2 && i1 < i2);
}

// ---------------------------------------------------------------------------
// Kernel A: init per-prior scratch (launch #1)
// ---------------------------------------------------------------------------
__global__ __launch_bounds__(256) void init_kernel(int Pp) {
    int p = blockIdx.x * 256 + threadIdx.x;
    if (p < Pp) { g_count[p] = 0; g_firstg[p] = 0x7FFFFFFF; }
}

// ---------------------------------------------------------------------------
// Kernel B: transpose cls_pred [P][80] -> g_clsT [80][P] (launch #2)
// ---------------------------------------------------------------------------
__global__ __launch_bounds__(256) void transpose_kernel(const float* __restrict__ cls, int Pp) {
    __shared__ float tile[32][NC + 1];
    int p0 = blockIdx.x * 32;
    int t = threadIdx.x;
    for (int i = t; i < 32 * NC; i += 256) {
        int pl = i / NC, c = i - pl * NC;
        int p = p0 + pl;
        tile[pl][c] = (p < Pp) ? cls[(size_t)p * NC + c] : 0.f;
    }
    __syncthreads();
    for (int i = t; i < NC * 32; i += 256) {
        int c = i >> 5, pl = i & 31;
        int p = p0 + pl;
        if (p < Pp) g_clsT[(size_t)c * MAXP + p] = tile[pl][c];
    }
}

// ---------------------------------------------------------------------------
// Kernel C: trivial reset (launch #3 -> keeps topk at profiled slot #4)
// ---------------------------------------------------------------------------
__global__ void reset_nlist_kernel() { g_nlist = 0; }

// ---------------------------------------------------------------------------
// Kernel D (launch #4): partial top-13 per (GT g, split s). One warp per GT,
// 8 GTs/block sharing one staged bbox tile (+ precomputed prior areas).
// Warp-global top-13 distributed in registers: lane j (j<13) holds rank j.
// PRUNED: since scores are in [0,1), m = score*iou^6 < iou^6, so
// 'iou6 > thr' gates the metric. ~96% of pairs have iou=0, so once thr>=0
// the score LDG almost never issues -> loop is 2 LDS + short FP chain.
// Zero-metric tie behavior is unchanged (early thr=-1 phase identical).
// ---------------------------------------------------------------------------
__global__ __launch_bounds__(TPB) void topk_partial_kernel(const float* __restrict__ bbox_pred,
                                                           const float* __restrict__ bbox_gt,
                                                           const int* __restrict__ label_gt,
                                                           int Pp, int Ngt, int ngrp) {
    __shared__ float4 btile[TILE];
    __shared__ float  spar[TILE];      // per-prior area, computed once per tile
    const unsigned FULL = 0xffffffffu;

    int grp = blockIdx.x % ngrp;       // GT group (fast-varying: same split co-resident)
    int s   = blockIdx.x / ngrp;
    int t = threadIdx.x;
    int w = t >> 5, lane = t & 31;
    int g = grp * 8 + w;
    int gc = (g < Ngt) ? g : Ngt - 1;

    const float4 gb = ((const float4*)bbox_gt)[gc];
    int cls = label_gt[gc] - 1;
    const float* __restrict__ srow = g_clsT + (size_t)cls * MAXP;
    const float gae = fmaxf(gb.z - gb.x, 0.f) * fmaxf(gb.w - gb.y, 0.f) + EPSV;

    int chunk = (Pp + NSPLIT - 1) / NSPLIT;
    int lo = s * chunk;
    int hi = min(lo + chunk, Pp);

    // distributed sorted list (desc); sentinels lose to any real metric (>=0)
    float lv = -1.f; int li = 0x7FFFFFFF;
    float thr = -1.f;                   // current 13th value (uniform across warp)

    const float4* __restrict__ bp = (const float4*)bbox_pred;
    for (int base = lo; base < hi; base += TILE) {
        int n = min(TILE, hi - base);
        __syncthreads();
        for (int i = t; i < n; i += TPB) {
            float4 b = bp[base + i];
            btile[i] = b;
            spar[i] = fmaxf(b.z - b.x, 0.f) * fmaxf(b.w - b.y, 0.f);
        }
        __syncthreads();

        for (int kk = 0; kk < n; kk += 32) {
            int j = kk + lane;
            int p = base + j;
            float m = -1.f;
            if (j < n) {
                float4 b = btile[j];
                float iw = fminf(gb.z, b.z) - fmaxf(gb.x, b.x);
                float ih = fminf(gb.w, b.w) - fmaxf(gb.y, b.y);
                float inter = fmaxf(iw, 0.f) * fmaxf(ih, 0.f);
                float denom = gae + spar[j] - inter;
                float iou = __fdividef(inter, denom);
                float i2 = iou * iou;
                float iou6 = i2 * i2 * i2;
                if (iou6 > thr) m = srow[p] * iou6;   // predicated LDG: rare once thr>=0
            }
            unsigned mask = __ballot_sync(FULL, m > thr);
            while (mask) {                           // rare insert path
                int src = __ffs(mask) - 1; mask &= mask - 1;   // ascending lane = ascending p
                float cm = __shfl_sync(FULL, m, src);
                int   cp = __shfl_sync(FULL, p, src);
                if (cm > thr) {                      // recheck vs possibly-raised thr (uniform)
                    unsigned bb = __ballot_sync(FULL, (lane < TOPK) && (cm > lv));
                    int pos = __ffs(bb) - 1;         // nonzero: lane 12 qualifies
                    float pv = __shfl_up_sync(FULL, lv, 1);
                    int   pi = __shfl_up_sync(FULL, li, 1);
                    if (lane < TOPK && lane >= pos) {
                        lv = (lane == pos) ? cm : pv;
                        li = (lane == pos) ? cp : pi;
                    }
                    thr = __shfl_sync(FULL, lv, TOPK - 1);
                }
            }
        }
    }

    // lanes 0..12 hold the sorted warp top-13
    if (g < Ngt && lane < TOPK) {
        size_t off = ((size_t)g * NSPLIT + s) * TOPK + lane;
        g_pval[off] = lv; g_pidx[off] = li;
    }
}

// ---------------------------------------------------------------------------
// Kernel E: merge NSPLIT partial lists per GT -> global top-13; mark counts;
// append contested priors (count reaching 2) to g_list.
// ---------------------------------------------------------------------------
__global__ __launch_bounds__(512) void topk_merge_kernel() {
    int g = blockIdx.x;
    int t = threadIdx.x;
    int w = t >> 5, lane = t & 31;
    const int NCAND = NSPLIT * TOPK;   // 416

    float cv = -2.f; int ci = 0x7FFFFFFF;
    if (t < NCAND) {
        cv = g_pval[(size_t)g * NCAND + t];
        ci = g_pidx[(size_t)g * NCAND + t];
    }

    __shared__ float sv[16]; __shared__ int si[16]; __shared__ int ss[16];
    __shared__ float selv0; __shared__ int seli[TOPK]; __shared__ int winner;

    for (int r = 0; r < TOPK; r++) {
        __syncthreads();
        float v = cv; int i = ci; int src = t;
        #pragma unroll
        for (int o = 16; o > 0; o >>= 1) {
            float ov = __shfl_xor_sync(0xffffffffu, v, o);
            int   oi = __shfl_xor_sync(0xffffffffu, i, o);
            int   os = __shfl_xor_sync(0xffffffffu, src, o);
            if (better(ov, oi, v, i)) { v = ov; i = oi; src = os; }
        }
        if (lane == 0) { sv[w] = v; si[w] = i; ss[w] = src; }
        __syncthreads();
        if (t < 32) {
            v = (t < 16) ? sv[t] : -3.f;
            i = (t < 16) ? si[t] : 0x7FFFFFFF;
            src = (t < 16) ? ss[t] : -1;
            #pragma unroll
            for (int o = 8; o > 0; o >>= 1) {
                float ov = __shfl_xor_sync(0xffffffffu, v, o);
                int   oi = __shfl_xor_sync(0xffffffffu, i, o);
                int   os = __shfl_xor_sync(0xffffffffu, src, o);
                if (better(ov, oi, v, i)) { v = ov; i = oi; src = os; }
            }
            if (t == 0) { if (r == 0) selv0 = v; seli[r] = i; winner = src; }
        }
        __syncthreads();
        if (t == winner) cv = -2.f;
    }
    __syncthreads();
    // keep-gate: if row max <= eps, reference drops all marks of this GT
    if (t < TOPK && selv0 > EPSV) {
        int p = seli[t];
        int old = atomicAdd(&g_count[p], 1);
        atomicMin(&g_firstg[p], g);
        if (old == 1) g_list[atomicAdd(&g_nlist, 1)] = p;   // exactly once per contested p
    }
}

// ---------------------------------------------------------------------------
// Kernel F: contested priors -> IoU argmax over GTs (first max wins)
// ---------------------------------------------------------------------------
__global__ __launch_bounds__(256) void resolve_kernel(const float* __restrict__ bbox_pred,
                                                      const float* __restrict__ bbox_gt,
                                                      int Ngt) {
    if ((int)blockIdx.x >= g_nlist) return;
    int p = g_list[blockIdx.x];
    int t = threadIdx.x;
    int w = t >> 5, lane = t & 31;

    float4 b = ((const float4*)bbox_pred)[p];
    float parea = fmaxf(b.z - b.x, 0.f) * fmaxf(b.w - b.y, 0.f);

    float cv = -1.f; int ci = t;
    if (t < Ngt) {
        float4 gb = ((const float4*)bbox_gt)[t];
        float iw = fminf(gb.z, b.z) - fmaxf(gb.x, b.x);
        float ih = fminf(gb.w, b.w) - fmaxf(gb.y, b.y);
        float inter = fmaxf(iw, 0.f) * fmaxf(ih, 0.f);
        float garea = fmaxf(gb.z - gb.x, 0.f) * fmaxf(gb.w - gb.y, 0.f);
        cv = __fdividef(inter, garea + parea - inter + EPSV);
    }
    __shared__ float sv[8]; __shared__ int si[8];
    #pragma unroll
    for (int o = 16; o > 0; o >>= 1) {
        float ov = __shfl_xor_sync(0xffffffffu, cv, o);
        int   oi = __shfl_xor_sync(0xffffffffu, ci, o);
        if (better(ov, oi, cv, ci)) { cv = ov; ci = oi; }
    }
    if (lane == 0) { sv[w] = cv; si[w] = ci; }
    __syncthreads();
    if (t < 8) {
        cv = sv[t]; ci = si[t];
        #pragma unroll
        for (int o = 4; o > 0; o >>= 1) {
            float ov = __shfl_xor_sync(0xffu, cv, o);
            int   oi = __shfl_xor_sync(0xffu, ci, o);
            if (better(ov, oi, cv, ci)) { cv = ov; ci = oi; }
        }
        if (t == 0) g_firstg[p] = ci;
    }
}

// ---------------------------------------------------------------------------
// Kernel G: outputs. layout: [P gt_index][P labels][P*80 one-hot][P*4 bboxes]
// ---------------------------------------------------------------------------
__global__ __launch_bounds__(256) void finalize_kernel(const float* __restrict__ bbox_gt,
                                                       const int* __restrict__ label_gt,
                                                       float* __restrict__ out,
                                                       int Pp, int Ngt) {
    __shared__ float4 gbox[MAXG];
    __shared__ int    glbl[MAXG];
    __shared__ int    s_cidx[256];
    int t = threadIdx.x;
    if (t < Ngt) { gbox[t] = ((const float4*)bbox_gt)[t]; glbl[t] = label_gt[t]; }
    __syncthreads();

    int pbase = blockIdx.x * 256;
    int p = pbase + t;
    int assigned = 0, lblout = 0;
    if (p < Pp) {
        int cnt = g_count[p];
        assigned = (cnt > 0) ? g_firstg[p] : 0;   // cnt>1 already resolved to argmax
        lblout   = (cnt > 0) ? glbl[assigned] : 0;
    }
    s_cidx[t] = (p < Pp) ? (glbl[assigned] - 1) : -1;
    __syncthreads();

    size_t o1 = (size_t)Pp;
    size_t o2 = (size_t)2 * Pp;
    size_t o3 = (size_t)2 * Pp + (size_t)NC * Pp;

    if (p < Pp) {
        out[p]      = (float)assigned;
        out[o1 + p] = (float)lblout;
        ((float4*)(out + o3))[p] = gbox[assigned];
    }
    float4* o2v = (float4*)(out + o2 + (size_t)pbase * NC);
    for (int e = t; e < 256 * NC / 4; e += 256) {
        int pl = e / (NC / 4);
        if (pbase + pl >= Pp) break;
        int c0 = (e - pl * (NC / 4)) * 4;
        int ci = s_cidx[pl];
        float4 v;
        v.x = (c0 + 0 == ci) ? 1.f : 0.f;
        v.y = (c0 + 1 == ci) ? 1.f : 0.f;
        v.z = (c0 + 2 == ci) ? 1.f : 0.f;
        v.w = (c0 + 3 == ci) ? 1.f : 0.f;
        o2v[e] = v;
    }
}

// ---------------------------------------------------------------------------
extern "C" void kernel_launch(void* const* d_in, const int* in_sizes, int n_in,
                              void* d_out, int out_size) {
    const float* cls_pred  = (const float*)d_in[0];
    const float* bbox_pred = (const float*)d_in[1];
    const int*   label_gt  = (const int*)d_in[2];
    const float* bbox_gt   = (const float*)d_in[3];
    float* out = (float*)d_out;

    int Pp  = in_sizes[1] / 4;   // 150000
    int Ngt = in_sizes[2];       // 256
    int ngrp = (Ngt + 7) / 8;    // 32

    init_kernel<<<(Pp + 255) / 256, 256>>>(Pp);                              // #1
    transpose_kernel<<<(Pp + 31) / 32, 256>>>(cls_pred, Pp);                 // #2
    reset_nlist_kernel<<<1, 1>>>();                                          // #3
    topk_partial_kernel<<<NSPLIT * ngrp, TPB>>>(bbox_pred, bbox_gt, label_gt,
                                                Pp, Ngt, ngrp);              // #4 (profiled)
    topk_merge_kernel<<<Ngt, 512>>>();                                       // #5
    resolve_kernel<<<MAXG * TOPK / 2 + 1, 256>>>(bbox_pred, bbox_gt, Ngt);   // #6
    finalize_kernel<<<(Pp + 255) / 256, 256>>>(bbox_gt, label_gt, out, Pp, Ngt); // #7
}

// round 17
// speedup vs baseline: 1.7549x; 1.1361x over previous
#include <cuda_runtime.h>
#include <cstdint>

#define MAXP   150016
#define NC     80
#define TOPK   13
#define EPSV   1e-9f
#define NSPLIT 32
#define TILE   1024
#define MAXG   256
#define TPB    256      // topk block: 8 GTs, 1 warp each

// Scratch (__device__ globals; no allocation allowed)
__device__ float g_clsT[(size_t)NC * MAXP];            // transposed scores [class][prior]
__device__ int   g_count[MAXP];
__device__ int   g_firstg[MAXP];
__device__ float g_pval[(size_t)MAXG * NSPLIT * TOPK];
__device__ int   g_pidx[(size_t)MAXG * NSPLIT * TOPK];
__device__ int   g_list[MAXG * TOPK / 2 + 8];
__device__ int   g_nlist;

__device__ __forceinline__ bool better(float v1, int i1, float v2, int i2) {
    // total order: value desc, index asc (lax.top_k / first-max-wins tie rule)
    return (v1 > v2) || (v1 == v2 && i1 < i2);
}

// conservative sixth root used for the hot-loop gate: t16 <= thr^(1/6)
__device__ __forceinline__ float sixth_root_cons(float thr) {
    if (thr > 0.f) return 0.999f * __powf(thr, 0.16666667f);
    return thr;   // thr==0 -> gate is inter>0 (exact); thr<0 -> gate always true
}

// ---------------------------------------------------------------------------
// Kernel A: init per-prior scratch (launch #1)
// ---------------------------------------------------------------------------
__global__ __launch_bounds__(256) void init_kernel(int Pp) {
    int p = blockIdx.x * 256 + threadIdx.x;
    if (p < Pp) { g_count[p] = 0; g_firstg[p] = 0x7FFFFFFF; }
}

// ---------------------------------------------------------------------------
// Kernel B: transpose cls_pred [P][80] -> g_clsT [80][P] (launch #2)
// ---------------------------------------------------------------------------
__global__ __launch_bounds__(256) void transpose_kernel(const float* __restrict__ cls, int Pp) {
    __shared__ float tile[32][NC + 1];
    int p0 = blockIdx.x * 32;
    int t = threadIdx.x;
    for (int i = t; i < 32 * NC; i += 256) {
        int pl = i / NC, c = i - pl * NC;
        int p = p0 + pl;
        tile[pl][c] = (p < Pp) ? cls[(size_t)p * NC + c] : 0.f;
    }
    __syncthreads();
    for (int i = t; i < NC * 32; i += 256) {
        int c = i >> 5, pl = i & 31;
        int p = p0 + pl;
        if (p < Pp) g_clsT[(size_t)c * MAXP + p] = tile[pl][c];
    }
}

// ---------------------------------------------------------------------------
// Kernel C: trivial reset (launch #3 -> keeps topk at profiled slot #4)
// ---------------------------------------------------------------------------
__global__ void reset_nlist_kernel() { g_nlist = 0; }

// ---------------------------------------------------------------------------
// Kernel D (launch #4): partial top-13 per (GT g, split s). One warp per GT,
// 8 GTs/block sharing one staged bbox tile (+ precomputed prior areas).
// Warp-global top-13 distributed in registers: lane j (j<13) holds rank j.
// DIVISION-FREE HOT LOOP: for thr>=0, iou^6>thr <=> inter > thr^(1/6)*denom.
// thr16 is a conservative (downward) sixth root updated only on the rare
// threshold change, so the gate admits a SUPERSET of true candidates; the
// exact iou6>thr and m>thr checks behind the warp-uniform ballot branch
// keep selection bit-identical to the previous rel_err=0.0 kernels.
// ---------------------------------------------------------------------------
__global__ __launch_bounds__(TPB) void topk_partial_kernel(const float* __restrict__ bbox_pred,
                                                           const float* __restrict__ bbox_gt,
                                                           const int* __restrict__ label_gt,
                                                           int Pp, int Ngt, int ngrp) {
    __shared__ float4 btile[TILE];
    __shared__ float  spar[TILE];      // per-prior area, computed once per tile
    const unsigned FULL = 0xffffffffu;

    int grp = blockIdx.x % ngrp;       // GT group (fast-varying: same split co-resident)
    int s   = blockIdx.x / ngrp;
    int t = threadIdx.x;
    int w = t >> 5, lane = t & 31;
    int g = grp * 8 + w;
    int gc = (g < Ngt) ? g : Ngt - 1;

    const float4 gb = ((const float4*)bbox_gt)[gc];
    int cls = label_gt[gc] - 1;
    const float* __restrict__ srow = g_clsT + (size_t)cls * MAXP;
    const float gae = fmaxf(gb.z - gb.x, 0.f) * fmaxf(gb.w - gb.y, 0.f) + EPSV;

    int chunk = (Pp + NSPLIT - 1) / NSPLIT;
    int lo = s * chunk;
    int hi = min(lo + chunk, Pp);

    // distributed sorted list (desc); sentinels lose to any real metric (>=0)
    float lv = -1.f; int li = 0x7FFFFFFF;
    float thr = -1.f;                   // current 13th metric value (uniform)
    float thr16 = -1.f;                 // conservative thr^(1/6) for the gate

    const float4* __restrict__ bp = (const float4*)bbox_pred;
    for (int base = lo; base < hi; base += TILE) {
        int n = min(TILE, hi - base);
        __syncthreads();
        for (int i = t; i < n; i += TPB) {
            float4 b = bp[base + i];
            btile[i] = b;
            spar[i] = fmaxf(b.z - b.x, 0.f) * fmaxf(b.w - b.y, 0.f);
        }
        __syncthreads();

        #pragma unroll 2
        for (int kk = 0; kk < n; kk += 32) {
            int j = kk + lane;
            float4 b = btile[j];
            float pa = spar[j];
            float iw = fminf(gb.z, b.z) - fmaxf(gb.x, b.x);
            float ih = fminf(gb.w, b.w) - fmaxf(gb.y, b.y);
            float inter = fmaxf(iw, 0.f) * fmaxf(ih, 0.f);
            float denom = gae + pa - inter;
            // cheap conservative gate (superset of iou6 > thr); masks tail lanes
            bool gate = (inter > thr16 * denom) && (j < n);
            unsigned gmask = __ballot_sync(FULL, gate);
            if (gmask) {                               // warp-uniform rare path
                int p = base + j;
                float m = -1.f;
                if (gate) {
                    float iou = __fdividef(inter, denom);
                    float i2 = iou * iou;
                    float iou6 = i2 * i2 * i2;
                    if (iou6 > thr) m = srow[p] * iou6;   // exact checks preserved
                }
                unsigned mask = __ballot_sync(FULL, m > thr);
                while (mask) {
                    int src = __ffs(mask) - 1; mask &= mask - 1;  // ascending lane = ascending p
                    float cm = __shfl_sync(FULL, m, src);
                    int   cp = __shfl_sync(FULL, p, src);
                    if (cm > thr) {                    // recheck vs possibly-raised thr
                        unsigned bb = __ballot_sync(FULL, (lane < TOPK) && (cm > lv));
                        int pos = __ffs(bb) - 1;
                        float pv = __shfl_up_sync(FULL, lv, 1);
                        int   pi = __shfl_up_sync(FULL, li, 1);
                        if (lane < TOPK && lane >= pos) {
                            lv = (lane == pos) ? cm : pv;
                            li = (lane == pos) ? cp : pi;
                        }
                        thr = __shfl_sync(FULL, lv, TOPK - 1);
                        thr16 = sixth_root_cons(thr);
                    }
                }
            }
        }
    }

    // lanes 0..12 hold the sorted warp top-13
    if (g < Ngt && lane < TOPK) {
        size_t off = ((size_t)g * NSPLIT + s) * TOPK + lane;
        g_pval[off] = lv; g_pidx[off] = li;
    }
}

// ---------------------------------------------------------------------------
// Kernel E: merge NSPLIT partial lists per GT -> global top-13; mark counts;
// append contested priors (count reaching 2) to g_list.
// ---------------------------------------------------------------------------
__global__ __launch_bounds__(512) void topk_merge_kernel() {
    int g = blockIdx.x;
    int t = threadIdx.x;
    int w = t >> 5, lane = t & 31;
    const int NCAND = NSPLIT * TOPK;   // 416

    float cv = -2.f; int ci = 0x7FFFFFFF;
    if (t < NCAND) {
        cv = g_pval[(size_t)g * NCAND + t];
        ci = g_pidx[(size_t)g * NCAND + t];
    }

    __shared__ float sv[16]; __shared__ int si[16]; __shared__ int ss[16];
    __shared__ float selv0; __shared__ int seli[TOPK]; __shared__ int winner;

    for (int r = 0; r < TOPK; r++) {
        __syncthreads();
        float v = cv; int i = ci; int src = t;
        #pragma unroll
        for (int o = 16; o > 0; o >>= 1) {
            float ov = __shfl_xor_sync(0xffffffffu, v, o);
            int   oi = __shfl_xor_sync(0xffffffffu, i, o);
            int   os = __shfl_xor_sync(0xffffffffu, src, o);
            if (better(ov, oi, v, i)) { v = ov; i = oi; src = os; }
        }
        if (lane == 0) { sv[w] = v; si[w] = i; ss[w] = src; }
        __syncthreads();
        if (t < 32) {
            v = (t < 16) ? sv[t] : -3.f;
            i = (t < 16) ? si[t] : 0x7FFFFFFF;
            src = (t < 16) ? ss[t] : -1;
            #pragma unroll
            for (int o = 8; o > 0; o >>= 1) {
                float ov = __shfl_xor_sync(0xffffffffu, v, o);
                int   oi = __shfl_xor_sync(0xffffffffu, i, o);
                int   os = __shfl_xor_sync(0xffffffffu, src, o);
                if (better(ov, oi, v, i)) { v = ov; i = oi; src = os; }
            }
            if (t == 0) { if (r == 0) selv0 = v; seli[r] = i; winner = src; }
        }
        __syncthreads();
        if (t == winner) cv = -2.f;
    }
    __syncthreads();
    // keep-gate: if row max <= eps, reference drops all marks of this GT
    if (t < TOPK && selv0 > EPSV) {
        int p = seli[t];
        int old = atomicAdd(&g_count[p], 1);
        atomicMin(&g_firstg[p], g);
        if (old == 1) g_list[atomicAdd(&g_nlist, 1)] = p;   // exactly once per contested p
    }
}

// ---------------------------------------------------------------------------
// Kernel F: contested priors -> IoU argmax over GTs (first max wins)
// ---------------------------------------------------------------------------
__global__ __launch_bounds__(256) void resolve_kernel(const float* __restrict__ bbox_pred,
                                                      const float* __restrict__ bbox_gt,
                                                      int Ngt) {
    if ((int)blockIdx.x >= g_nlist) return;
    int p = g_list[blockIdx.x];
    int t = threadIdx.x;
    int w = t >> 5, lane = t & 31;

    float4 b = ((const float4*)bbox_pred)[p];
    float parea = fmaxf(b.z - b.x, 0.f) * fmaxf(b.w - b.y, 0.f);

    float cv = -1.f; int ci = t;
    if (t < Ngt) {
        float4 gb = ((const float4*)bbox_gt)[t];
        float iw = fminf(gb.z, b.z) - fmaxf(gb.x, b.x);
        float ih = fminf(gb.w, b.w) - fmaxf(gb.y, b.y);
        float inter = fmaxf(iw, 0.f) * fmaxf(ih, 0.f);
        float garea = fmaxf(gb.z - gb.x, 0.f) * fmaxf(gb.w - gb.y, 0.f);
        cv = __fdividef(inter, garea + parea - inter + EPSV);
    }
    __shared__ float sv[8]; __shared__ int si[8];
    #pragma unroll
    for (int o = 16; o > 0; o >>= 1) {
        float ov = __shfl_xor_sync(0xffffffffu, cv, o);
        int   oi = __shfl_xor_sync(0xffffffffu, ci, o);
        if (better(ov, oi, cv, ci)) { cv = ov; ci = oi; }
    }
    if (lane == 0) { sv[w] = cv; si[w] = ci; }
    __syncthreads();
    if (t < 8) {
        cv = sv[t]; ci = si[t];
        #pragma unroll
        for (int o = 4; o > 0; o >>= 1) {
            float ov = __shfl_xor_sync(0xffu, cv, o);
            int   oi = __shfl_xor_sync(0xffu, ci, o);
            if (better(ov, oi, cv, ci)) { cv = ov; ci = oi; }
        }
        if (t == 0) g_firstg[p] = ci;
    }
}

// ---------------------------------------------------------------------------
// Kernel G: outputs. layout: [P gt_index][P labels][P*80 one-hot][P*4 bboxes]
// ---------------------------------------------------------------------------
__global__ __launch_bounds__(256) void finalize_kernel(const float* __restrict__ bbox_gt,
                                                       const int* __restrict__ label_gt,
                                                       float* __restrict__ out,
                                                       int Pp, int Ngt) {
    __shared__ float4 gbox[MAXG];
    __shared__ int    glbl[MAXG];
    __shared__ int    s_cidx[256];
    int t = threadIdx.x;
    if (t < Ngt) { gbox[t] = ((const float4*)bbox_gt)[t]; glbl[t] = label_gt[t]; }
    __syncthreads();

    int pbase = blockIdx.x * 256;
    int p = pbase + t;
    int assigned = 0, lblout = 0;
    if (p < Pp) {
        int cnt = g_count[p];
        assigned = (cnt > 0) ? g_firstg[p] : 0;   // cnt>1 already resolved to argmax
        lblout   = (cnt > 0) ? glbl[assigned] : 0;
    }
    s_cidx[t] = (p < Pp) ? (glbl[assigned] - 1) : -1;
    __syncthreads();

    size_t o1 = (size_t)Pp;
    size_t o2 = (size_t)2 * Pp;
    size_t o3 = (size_t)2 * Pp + (size_t)NC * Pp;

    if (p < Pp) {
        out[p]      = (float)assigned;
        out[o1 + p] = (float)lblout;
        ((float4*)(out + o3))[p] = gbox[assigned];
    }
    float4* o2v = (float4*)(out + o2 + (size_t)pbase * NC);
    for (int e = t; e < 256 * NC / 4; e += 256) {
        int pl = e / (NC / 4);
        if (pbase + pl >= Pp) break;
        int c0 = (e - pl * (NC / 4)) * 4;
        int ci = s_cidx[pl];
        float4 v;
        v.x = (c0 + 0 == ci) ? 1.f : 0.f;
        v.y = (c0 + 1 == ci) ? 1.f : 0.f;
        v.z = (c0 + 2 == ci) ? 1.f : 0.f;
        v.w = (c0 + 3 == ci) ? 1.f : 0.f;
        o2v[e] = v;
    }
}

// ---------------------------------------------------------------------------
extern "C" void kernel_launch(void* const* d_in, const int* in_sizes, int n_in,
                              void* d_out, int out_size) {
    const float* cls_pred  = (const float*)d_in[0];
    const float* bbox_pred = (const float*)d_in[1];
    const int*   label_gt  = (const int*)d_in[2];
    const float* bbox_gt   = (const float*)d_in[3];
    float* out = (float*)d_out;

    int Pp  = in_sizes[1] / 4;   // 150000
    int Ngt = in_sizes[2];       // 256
    int ngrp = (Ngt + 7) / 8;    // 32

    init_kernel<<<(Pp + 255) / 256, 256>>>(Pp);                              // #1
    transpose_kernel<<<(Pp + 31) / 32, 256>>>(cls_pred, Pp);                 // #2
    reset_nlist_kernel<<<1, 1>>>();                                          // #3
    topk_partial_kernel<<<NSPLIT * ngrp, TPB>>>(bbox_pred, bbox_gt, label_gt,
                                                Pp, Ngt, ngrp);              // #4 (profiled)
    topk_merge_kernel<<<Ngt, 512>>>();                                       // #5
    resolve_kernel<<<MAXG * TOPK / 2 + 1, 256>>>(bbox_pred, bbox_gt, Ngt);   // #6
    finalize_kernel<<<(Pp + 255) / 256, 256>>>(bbox_gt, label_gt, out, Pp, Ngt); // #7
}